// round 9
// baseline (speedup 1.0000x reference)
#include <cuda_runtime.h>
#include <cuda_fp16.h>
#include <math.h>
#include <stdint.h>

#define N_TOK 8192
#define DIM   1024
#define NE    8
#define NR    (N_TOK * 2)

typedef uint32_t u32;

// ---------------- scratch (device globals; no allocation) ----------------
__device__ int    g_counts[NE];
__device__ int    g_offsets[NE];
__device__ int    g_cursor[NE];
__device__ int    g_tope[NR];
__device__ float  g_topw[NR];
__device__ int    g_slot[NR];                          // (token,j) -> routed slot
__device__ int    g_rows[NR + 128];
__device__ __half g_xh[(size_t)N_TOK * DIM];           // x in fp16
__device__ __half g_h[(size_t)(NR + 128) * DIM];       // hidden acts, fp16
__device__ float  g_ye[(size_t)(NR + 128) * DIM];      // expert outputs, fp32
__device__ __half g_wt[2][NE][DIM][DIM];               // W^T [n][k], fp16

// ---------------- init ----------------
__global__ void init_kernel() {
    int t = threadIdx.x;
    if (t < NE) { g_counts[t] = 0; g_cursor[t] = 0; }
}

// ---------------- gate (also emits x_fp16) ----------------
__global__ void gate_kernel(const float* __restrict__ x,
                            const float* __restrict__ Wg,
                            const float* __restrict__ bg,
                            float* __restrict__ gate_out) {
    int warp = threadIdx.x >> 5;
    int lane = threadIdx.x & 31;
    int t = blockIdx.x * (blockDim.x >> 5) + warp;
    if (t >= N_TOK) return;

    const float* xr = x + (size_t)t * DIM;
    float acc[NE];
#pragma unroll
    for (int e = 0; e < NE; e++) acc[e] = 0.f;
#pragma unroll
    for (int i = 0; i < DIM / 128; i++) {
        int k0 = i * 128 + lane * 4;
        float4 xv = *(const float4*)(xr + k0);
        __half2 h01 = __halves2half2(__float2half_rn(xv.x), __float2half_rn(xv.y));
        __half2 h23 = __halves2half2(__float2half_rn(xv.z), __float2half_rn(xv.w));
        *(__half2*)(&g_xh[(size_t)t * DIM + k0])     = h01;
        *(__half2*)(&g_xh[(size_t)t * DIM + k0 + 2]) = h23;

        float xa[4] = {xv.x, xv.y, xv.z, xv.w};
#pragma unroll
        for (int c = 0; c < 4; c++) {
            const float4 w0 = *(const float4*)(Wg + (size_t)(k0 + c) * NE);
            const float4 w1 = *(const float4*)(Wg + (size_t)(k0 + c) * NE + 4);
            acc[0] += xa[c] * w0.x;  acc[1] += xa[c] * w0.y;
            acc[2] += xa[c] * w0.z;  acc[3] += xa[c] * w0.w;
            acc[4] += xa[c] * w1.x;  acc[5] += xa[c] * w1.y;
            acc[6] += xa[c] * w1.z;  acc[7] += xa[c] * w1.w;
        }
    }
#pragma unroll
    for (int e = 0; e < NE; e++)
#pragma unroll
        for (int o = 16; o > 0; o >>= 1)
            acc[e] += __shfl_xor_sync(0xffffffffu, acc[e], o);

    if (lane == 0) {
        float l[NE], p[NE];
        float m = -1e30f;
#pragma unroll
        for (int e = 0; e < NE; e++) { l[e] = acc[e] + bg[e]; m = fmaxf(m, l[e]); }
        float s = 0.f;
#pragma unroll
        for (int e = 0; e < NE; e++) { p[e] = expf(l[e] - m); s += p[e]; }
        float inv = 1.f / s;
#pragma unroll
        for (int e = 0; e < NE; e++) { p[e] *= inv; gate_out[(size_t)t * NE + e] = p[e]; }

        int e0 = 0; float p0 = p[0];
#pragma unroll
        for (int e = 1; e < NE; e++) if (p[e] > p0) { p0 = p[e]; e0 = e; }
        int e1 = -1; float p1 = -1e30f;
#pragma unroll
        for (int e = 0; e < NE; e++) if (e != e0 && p[e] > p1) { p1 = p[e]; e1 = e; }

        float d  = p1 - p0;
        float ex = expf(d);
        float w0 = 1.f / (1.f + ex);
        float w1 = ex  / (1.f + ex);

        g_tope[2 * t + 0] = e0;  g_topw[2 * t + 0] = w0;
        g_tope[2 * t + 1] = e1;  g_topw[2 * t + 1] = w1;
        atomicAdd(&g_counts[e0], 1);
        atomicAdd(&g_counts[e1], 1);
    }
}

__global__ void scan_kernel() {
    if (threadIdx.x == 0) {
        int s = 0;
        for (int e = 0; e < NE; e++) { g_offsets[e] = s; s += g_counts[e]; }
    }
}

__global__ void route_kernel() {
    int i = blockIdx.x * blockDim.x + threadIdx.x;
    if (i >= NR) return;
    int e = g_tope[i];
    int pos  = atomicAdd(&g_cursor[e], 1);
    int slot = g_offsets[e] + pos;
    g_rows[slot] = i >> 1;
    g_slot[i]    = slot;
}

// ---------------- W transpose + fp16 convert (half2 stores) ----------------
__global__ void convert_w_kernel(const float* __restrict__ W1,
                                 const float* __restrict__ W2) {
    __shared__ float t[64][33];
    int z = blockIdx.z;               // layer*8 + e
    int layer = z >> 3, e = z & 7;
    int k0 = blockIdx.x * 64, n0 = blockIdx.y * 32;
    int tx = threadIdx.x & 31, ty = threadIdx.x >> 5;   // 32 x 8

    const float* src = (layer ? W2 : W1) + (size_t)e * DIM * DIM;
#pragma unroll
    for (int i = 0; i < 8; i++) {
        int kk = ty + i * 8;
        t[kk][tx] = src[(size_t)(k0 + kk) * DIM + n0 + tx];
    }
    __syncthreads();
    __half* dst = &g_wt[layer][e][0][0];
#pragma unroll
    for (int i = 0; i < 4; i++) {
        int nn = ty + i * 8;
        __half2 v = __halves2half2(__float2half_rn(t[2 * tx][nn]),
                                   __float2half_rn(t[2 * tx + 1][nn]));
        *(__half2*)(dst + (size_t)(n0 + nn) * DIM + k0 + 2 * tx) = v;
    }
}

// ---------------- HMMA GEMM: cp.async 4-stage pipeline --------------------
// CTA 128x128, BK=32, 8 warps (4 M x 2 N), warp tile 32x64, m16n8k16.
#define BK      32
#define SRD     40                    // smem row stride in halfs (conflict-free)
#define TILE_H  (128 * SRD)           // 5120 halfs per matrix
#define A_O     0
#define B_O     TILE_H
#define STG_H   (2 * TILE_H)          // 10240 halfs = 20KB per stage
#define STAGES  4
#define SMEM_B  (STAGES * STG_H * 2)  // 80KB

#define CP_ASYNC16(dst, src) \
    asm volatile("cp.async.cg.shared.global [%0], [%1], 16;" \
        :: "r"(dst), "l"(src) : "memory")
#define CP_COMMIT() asm volatile("cp.async.commit_group;" ::: "memory")
#define CP_WAIT2()  asm volatile("cp.async.wait_group 2;"  ::: "memory")

#define MMA16816(d, a0, a1, a2, a3, b0, b1) \
    asm volatile("mma.sync.aligned.m16n8k16.row.col.f32.f16.f16.f32 " \
        "{%0,%1,%2,%3}, {%4,%5,%6,%7}, {%8,%9}, {%0,%1,%2,%3};" \
        : "+f"((d)[0]), "+f"((d)[1]), "+f"((d)[2]), "+f"((d)[3]) \
        : "r"(a0), "r"(a1), "r"(a2), "r"(a3), "r"(b0), "r"(b1))

__device__ __forceinline__ u32 smem_u32(const void* p) {
    u32 a;
    asm("{ .reg .u64 t; cvta.to.shared.u64 t, %1; cvt.u32.u64 %0, t; }" : "=r"(a) : "l"(p));
    return a;
}

template<int LAYER>
__global__ void __launch_bounds__(256, 2) moe_hmma_kernel(
        const float* __restrict__ bias) {
    const int e = blockIdx.z;
    const int M = g_counts[e];
    const int row0 = blockIdx.y * 128;
    if (row0 >= M) return;
    const int base = g_offsets[e];
    const int bn0  = blockIdx.x * 128;
    const float* bp = bias + (size_t)e * DIM;

    extern __shared__ __half sh[];
    const u32 sb = smem_u32(sh);

    const int tid = threadIdx.x;
    const int wid = tid >> 5, lane = tid & 31;
    const int wm = wid >> 1, wn = wid & 1;
    const int g = lane >> 2, q = lane & 3;

    // ---- loader role: thread t -> row r, 16-half chunk ks ----
    const int r   = tid >> 1;
    const int ks  = (tid & 1) * 16;
    const int rL  = row0 + r;
    const int rr  = (rL < M) ? rL : 0;
    const __half* arow;
    if (LAYER == 1) arow = g_xh + (size_t)g_rows[base + rr] * DIM;
    else            arow = g_h + (size_t)(base + rr) * DIM;
    const __half* brow = &g_wt[LAYER - 1][e][bn0 + r][0];

    const u32 dA = sb + (u32)(A_O + r * SRD + ks) * 2;
    const u32 dB = sb + (u32)(B_O + r * SRD + ks) * 2;

    float acc[16][4];
#pragma unroll
    for (int i = 0; i < 16; i++)
#pragma unroll
        for (int j = 0; j < 4; j++) acc[i][j] = 0.f;

    auto ISSUE = [&](int c) {
        const u32 so = (u32)((c & (STAGES - 1)) * STG_H) * 2;
        const int k0 = c * BK + ks;
        CP_ASYNC16(dA + so,      arow + k0);
        CP_ASYNC16(dA + so + 16, arow + k0 + 8);
        CP_ASYNC16(dB + so,      brow + k0);
        CP_ASYNC16(dB + so + 16, brow + k0 + 8);
    };

#pragma unroll
    for (int s = 0; s < STAGES - 1; s++) { ISSUE(s); CP_COMMIT(); }

    const int NSTG = DIM / BK;   // 32
    for (int c = 0; c < NSTG; c++) {
        CP_WAIT2();
        __syncthreads();
        if (c + STAGES - 1 < NSTG) ISSUE(c + STAGES - 1);
        CP_COMMIT();

        const __half* p = sh + (c & (STAGES - 1)) * STG_H;
#pragma unroll
        for (int k16 = 0; k16 < 2; k16++) {
            u32 af[2][4];
#pragma unroll
            for (int ms = 0; ms < 2; ms++) {
                int ab = (wm * 32 + ms * 16 + g) * SRD + k16 * 16 + q * 2;
                const __half* ap = p + A_O + ab;
                af[ms][0] = *(const u32*)(ap);
                af[ms][1] = *(const u32*)(ap + 8 * SRD);
                af[ms][2] = *(const u32*)(ap + 8);
                af[ms][3] = *(const u32*)(ap + 8 * SRD + 8);
            }
            u32 bf[8][2];
#pragma unroll
            for (int nt = 0; nt < 8; nt++) {
                int bb = (wn * 64 + nt * 8 + g) * SRD + k16 * 16 + q * 2;
                bf[nt][0] = *(const u32*)(p + B_O + bb);
                bf[nt][1] = *(const u32*)(p + B_O + bb + 8);
            }
#pragma unroll
            for (int nt = 0; nt < 8; nt++)
#pragma unroll
                for (int ms = 0; ms < 2; ms++)
                    MMA16816(acc[ms * 8 + nt],
                             af[ms][0], af[ms][1], af[ms][2], af[ms][3],
                             bf[nt][0], bf[nt][1]);
        }
    }

    // ---- epilogue ----
#pragma unroll
    for (int ms = 0; ms < 2; ms++) {
#pragma unroll
        for (int half = 0; half < 2; half++) {
            int rloc = row0 + wm * 32 + ms * 16 + g + half * 8;
            if (rloc >= M) continue;
            int gslot = base + rloc;
            if (LAYER == 1) {
                __half* hrow = g_h + (size_t)gslot * DIM;
#pragma unroll
                for (int nt = 0; nt < 8; nt++) {
                    int col = bn0 + wn * 64 + nt * 8 + q * 2;
                    float b0 = bp[col], b1 = bp[col + 1];
                    float v0 = fmaxf(acc[ms * 8 + nt][half * 2 + 0] + b0, 0.f);
                    float v1 = fmaxf(acc[ms * 8 + nt][half * 2 + 1] + b1, 0.f);
                    *(__half2*)(hrow + col) =
                        __halves2half2(__float2half_rn(v0), __float2half_rn(v1));
                }
            } else {
                float* yrow = g_ye + (size_t)gslot * DIM;
#pragma unroll
                for (int nt = 0; nt < 8; nt++) {
                    int col = bn0 + wn * 64 + nt * 8 + q * 2;
                    float b0 = bp[col], b1 = bp[col + 1];
                    *(float2*)(yrow + col) =
                        make_float2(acc[ms * 8 + nt][half * 2 + 0] + b0,
                                    acc[ms * 8 + nt][half * 2 + 1] + b1);
                }
            }
        }
    }
}

// ---------------- combine: y[t] = w0*ye[slot0] + w1*ye[slot1] ----------------
__global__ void combine_kernel(float* __restrict__ y) {
    int idx = blockIdx.x * blockDim.x + threadIdx.x;    // over N_TOK * DIM/4
    int t  = idx >> 8;                                  // DIM/4 = 256
    int c4 = (idx & 255) * 4;
    float w0 = g_topw[2 * t],     w1 = g_topw[2 * t + 1];
    int   s0 = g_slot[2 * t],     s1 = g_slot[2 * t + 1];
    float4 a = *(const float4*)(g_ye + (size_t)s0 * DIM + c4);
    float4 b = *(const float4*)(g_ye + (size_t)s1 * DIM + c4);
    float4 v;
    v.x = w0 * a.x + w1 * b.x;
    v.y = w0 * a.y + w1 * b.y;
    v.z = w0 * a.z + w1 * b.z;
    v.w = w0 * a.w + w1 * b.w;
    *(float4*)(y + (size_t)t * DIM + c4) = v;
}

// ---------------- launch ----------------
extern "C" void kernel_launch(void* const* d_in, const int* in_sizes, int n_in,
                              void* d_out, int out_size) {
    const float* x  = (const float*)d_in[0];
    const float* Wg = (const float*)d_in[1];
    const float* bg = (const float*)d_in[2];
    const float* W1 = (const float*)d_in[3];
    const float* b1 = (const float*)d_in[4];
    const float* W2 = (const float*)d_in[5];
    const float* b2 = (const float*)d_in[6];

    float* y        = (float*)d_out;
    float* gate_out = (float*)d_out + (size_t)N_TOK * DIM;

    static int attr_done = 0;
    if (!attr_done) {
        cudaFuncSetAttribute(moe_hmma_kernel<1>,
            cudaFuncAttributeMaxDynamicSharedMemorySize, SMEM_B);
        cudaFuncSetAttribute(moe_hmma_kernel<2>,
            cudaFuncAttributeMaxDynamicSharedMemorySize, SMEM_B);
        attr_done = 1;
    }

    init_kernel<<<1, 32>>>();
    convert_w_kernel<<<dim3(DIM / 64, DIM / 32, 16), 256>>>(W1, W2);
    gate_kernel<<<N_TOK / 8, 256>>>(x, Wg, bg, gate_out);
    scan_kernel<<<1, 1>>>();
    route_kernel<<<NR / 256, 256>>>();

    dim3 grid(DIM / 128, NR / 128, NE);
    moe_hmma_kernel<1><<<grid, 256, SMEM_B>>>(b1);
    moe_hmma_kernel<2><<<grid, 256, SMEM_B>>>(b2);
    combine_kernel<<<(N_TOK * DIM / 4) / 256, 256>>>(y);
}

// round 10
// speedup vs baseline: 1.1174x; 1.1174x over previous
#include <cuda_runtime.h>
#include <cuda_fp16.h>
#include <math.h>
#include <stdint.h>

#define N_TOK 8192
#define DIM   1024
#define NE    8
#define NR    (N_TOK * 2)

typedef uint32_t u32;

// ---------------- scratch (device globals; no allocation) ----------------
__device__ int    g_counts[NE];
__device__ int    g_offsets[NE];
__device__ int    g_cursor[NE];
__device__ int    g_tope[NR];
__device__ float  g_topw[NR];
__device__ int    g_slot[NR];                          // (token,j) -> routed slot
__device__ int    g_rows[NR + 128];
__device__ __half g_xh[(size_t)N_TOK * DIM];           // x in fp16
__device__ __half g_h[(size_t)(NR + 128) * DIM];       // hidden acts, fp16
__device__ float  g_ye[(size_t)(NR + 128) * DIM];      // expert outputs, fp32
__device__ __half g_wt[2][NE][DIM][DIM];               // W^T [n][k], fp16

// ---------------- init ----------------
__global__ void init_kernel() {
    int t = threadIdx.x;
    if (t < NE) { g_counts[t] = 0; g_cursor[t] = 0; }
}

// ---------------- gate (also emits x_fp16) ----------------
__global__ void gate_kernel(const float* __restrict__ x,
                            const float* __restrict__ Wg,
                            const float* __restrict__ bg,
                            float* __restrict__ gate_out) {
    int warp = threadIdx.x >> 5;
    int lane = threadIdx.x & 31;
    int t = blockIdx.x * (blockDim.x >> 5) + warp;
    if (t >= N_TOK) return;

    const float* xr = x + (size_t)t * DIM;
    float acc[NE];
#pragma unroll
    for (int e = 0; e < NE; e++) acc[e] = 0.f;
#pragma unroll
    for (int i = 0; i < DIM / 128; i++) {
        int k0 = i * 128 + lane * 4;
        float4 xv = *(const float4*)(xr + k0);
        __half2 h01 = __halves2half2(__float2half_rn(xv.x), __float2half_rn(xv.y));
        __half2 h23 = __halves2half2(__float2half_rn(xv.z), __float2half_rn(xv.w));
        *(__half2*)(&g_xh[(size_t)t * DIM + k0])     = h01;
        *(__half2*)(&g_xh[(size_t)t * DIM + k0 + 2]) = h23;

        float xa[4] = {xv.x, xv.y, xv.z, xv.w};
#pragma unroll
        for (int c = 0; c < 4; c++) {
            const float4 w0 = *(const float4*)(Wg + (size_t)(k0 + c) * NE);
            const float4 w1 = *(const float4*)(Wg + (size_t)(k0 + c) * NE + 4);
            acc[0] += xa[c] * w0.x;  acc[1] += xa[c] * w0.y;
            acc[2] += xa[c] * w0.z;  acc[3] += xa[c] * w0.w;
            acc[4] += xa[c] * w1.x;  acc[5] += xa[c] * w1.y;
            acc[6] += xa[c] * w1.z;  acc[7] += xa[c] * w1.w;
        }
    }
#pragma unroll
    for (int e = 0; e < NE; e++)
#pragma unroll
        for (int o = 16; o > 0; o >>= 1)
            acc[e] += __shfl_xor_sync(0xffffffffu, acc[e], o);

    if (lane == 0) {
        float l[NE], p[NE];
        float m = -1e30f;
#pragma unroll
        for (int e = 0; e < NE; e++) { l[e] = acc[e] + bg[e]; m = fmaxf(m, l[e]); }
        float s = 0.f;
#pragma unroll
        for (int e = 0; e < NE; e++) { p[e] = expf(l[e] - m); s += p[e]; }
        float inv = 1.f / s;
#pragma unroll
        for (int e = 0; e < NE; e++) { p[e] *= inv; gate_out[(size_t)t * NE + e] = p[e]; }

        int e0 = 0; float p0 = p[0];
#pragma unroll
        for (int e = 1; e < NE; e++) if (p[e] > p0) { p0 = p[e]; e0 = e; }
        int e1 = -1; float p1 = -1e30f;
#pragma unroll
        for (int e = 0; e < NE; e++) if (e != e0 && p[e] > p1) { p1 = p[e]; e1 = e; }

        float d  = p1 - p0;
        float ex = expf(d);
        float w0 = 1.f / (1.f + ex);
        float w1 = ex  / (1.f + ex);

        g_tope[2 * t + 0] = e0;  g_topw[2 * t + 0] = w0;
        g_tope[2 * t + 1] = e1;  g_topw[2 * t + 1] = w1;
        atomicAdd(&g_counts[e0], 1);
        atomicAdd(&g_counts[e1], 1);
    }
}

__global__ void scan_kernel() {
    if (threadIdx.x == 0) {
        int s = 0;
        for (int e = 0; e < NE; e++) { g_offsets[e] = s; s += g_counts[e]; }
    }
}

__global__ void route_kernel() {
    int i = blockIdx.x * blockDim.x + threadIdx.x;
    if (i >= NR) return;
    int e = g_tope[i];
    int pos  = atomicAdd(&g_cursor[e], 1);
    int slot = g_offsets[e] + pos;
    g_rows[slot] = i >> 1;
    g_slot[i]    = slot;
}

// ---------------- W transpose + fp16 convert (half2 stores) ----------------
__global__ void convert_w_kernel(const float* __restrict__ W1,
                                 const float* __restrict__ W2) {
    __shared__ float t[64][33];
    int z = blockIdx.z;               // layer*8 + e
    int layer = z >> 3, e = z & 7;
    int k0 = blockIdx.x * 64, n0 = blockIdx.y * 32;
    int tx = threadIdx.x & 31, ty = threadIdx.x >> 5;   // 32 x 8

    const float* src = (layer ? W2 : W1) + (size_t)e * DIM * DIM;
#pragma unroll
    for (int i = 0; i < 8; i++) {
        int kk = ty + i * 8;
        t[kk][tx] = src[(size_t)(k0 + kk) * DIM + n0 + tx];
    }
    __syncthreads();
    __half* dst = &g_wt[layer][e][0][0];
#pragma unroll
    for (int i = 0; i < 4; i++) {
        int nn = ty + i * 8;
        __half2 v = __halves2half2(__float2half_rn(t[2 * tx][nn]),
                                   __float2half_rn(t[2 * tx + 1][nn]));
        *(__half2*)(dst + (size_t)(n0 + nn) * DIM + k0 + 2 * tx) = v;
    }
}

// ---------------- HMMA GEMM: cp.async pipeline + ldmatrix ------------------
// CTA 128x128, BK=32, 8 warps (4 M x 2 N), warp tile 32x64, m16n8k16.
#define BK      32
#define SRD     40                    // smem row stride in halfs (conflict-free)
#define TILE_H  (128 * SRD)           // 5120 halfs per matrix
#define A_O     0
#define B_O     TILE_H
#define STG_H   (2 * TILE_H)          // 10240 halfs = 20KB per stage
#define STAGES  4
#define SMEM_B  (STAGES * STG_H * 2)  // 80KB

#define CP_ASYNC16(dst, src) \
    asm volatile("cp.async.cg.shared.global [%0], [%1], 16;" \
        :: "r"(dst), "l"(src) : "memory")
#define CP_COMMIT() asm volatile("cp.async.commit_group;" ::: "memory")
#define CP_WAIT2()  asm volatile("cp.async.wait_group 2;"  ::: "memory")

#define MMA16816(d, a0, a1, a2, a3, b0, b1) \
    asm volatile("mma.sync.aligned.m16n8k16.row.col.f32.f16.f16.f32 " \
        "{%0,%1,%2,%3}, {%4,%5,%6,%7}, {%8,%9}, {%0,%1,%2,%3};" \
        : "+f"((d)[0]), "+f"((d)[1]), "+f"((d)[2]), "+f"((d)[3]) \
        : "r"(a0), "r"(a1), "r"(a2), "r"(a3), "r"(b0), "r"(b1))

#define LDSM_X4(r0, r1, r2, r3, addr) \
    asm volatile("ldmatrix.sync.aligned.m8n8.x4.shared.b16 {%0,%1,%2,%3}, [%4];" \
        : "=r"(r0), "=r"(r1), "=r"(r2), "=r"(r3) : "r"(addr))

__device__ __forceinline__ u32 smem_u32(const void* p) {
    u32 a;
    asm("{ .reg .u64 t; cvta.to.shared.u64 t, %1; cvt.u32.u64 %0, t; }" : "=r"(a) : "l"(p));
    return a;
}

template<int LAYER>
__global__ void __launch_bounds__(256, 2) moe_hmma_kernel(
        const float* __restrict__ bias) {
    const int e = blockIdx.z;
    const int M = g_counts[e];
    const int row0 = blockIdx.y * 128;
    if (row0 >= M) return;
    const int base = g_offsets[e];
    const int bn0  = blockIdx.x * 128;
    const float* bp = bias + (size_t)e * DIM;

    extern __shared__ __half sh[];
    const u32 sb = smem_u32(sh);

    const int tid = threadIdx.x;
    const int wid = tid >> 5, lane = tid & 31;
    const int wm = wid >> 1, wn = wid & 1;
    const int g = lane >> 2, q = lane & 3;

    // ---- loader role: thread t -> row r, 16-half chunk ks ----
    const int r   = tid >> 1;
    const int ks  = (tid & 1) * 16;
    const int rL  = row0 + r;
    const int rr  = (rL < M) ? rL : 0;
    const __half* arow;
    if (LAYER == 1) arow = g_xh + (size_t)g_rows[base + rr] * DIM;
    else            arow = g_h + (size_t)(base + rr) * DIM;
    const __half* brow = &g_wt[LAYER - 1][e][bn0 + r][0];

    const u32 dA = sb + (u32)(A_O + r * SRD + ks) * 2;
    const u32 dB = sb + (u32)(B_O + r * SRD + ks) * 2;

    // ---- ldmatrix per-lane byte offsets (within a stage) ----
    // A (per ms): matrices (rows0-7,k0)(rows8-15,k0)(rows0-7,k8)(rows8-15,k8)
    u32 a_lm[2];
#pragma unroll
    for (int ms = 0; ms < 2; ms++)
        a_lm[ms] = (u32)((A_O + (wm * 32 + ms * 16 + (lane & 15)) * SRD
                          + (lane >> 4) * 8) * 2);
    // B (per j = nt pair): m0=(nt=2j,k0) m1=(nt=2j,k8) m2=(nt=2j+1,k0) m3=(nt=2j+1,k8)
    u32 b_lm[4];
#pragma unroll
    for (int j = 0; j < 4; j++)
        b_lm[j] = (u32)((B_O + (wn * 64 + j * 16 + (lane & 7) + ((lane >> 4) & 1) * 8) * SRD
                         + ((lane >> 3) & 1) * 8) * 2);

    float acc[16][4];
#pragma unroll
    for (int i = 0; i < 16; i++)
#pragma unroll
        for (int j = 0; j < 4; j++) acc[i][j] = 0.f;

    auto ISSUE = [&](int c) {
        const u32 so = (u32)((c & (STAGES - 1)) * STG_H) * 2;
        const int k0 = c * BK + ks;
        CP_ASYNC16(dA + so,      arow + k0);
        CP_ASYNC16(dA + so + 16, arow + k0 + 8);
        CP_ASYNC16(dB + so,      brow + k0);
        CP_ASYNC16(dB + so + 16, brow + k0 + 8);
    };

#pragma unroll
    for (int s = 0; s < STAGES - 1; s++) { ISSUE(s); CP_COMMIT(); }

    const int NSTG = DIM / BK;   // 32
    for (int c = 0; c < NSTG; c++) {
        CP_WAIT2();
        __syncthreads();
        if (c + STAGES - 1 < NSTG) ISSUE(c + STAGES - 1);
        CP_COMMIT();

        const u32 pb = sb + (u32)((c & (STAGES - 1)) * STG_H) * 2;
#pragma unroll
        for (int k16 = 0; k16 < 2; k16++) {
            const u32 kb = (u32)(k16 * 32);   // 16 halfs = 32 bytes
            u32 af[2][4];
            LDSM_X4(af[0][0], af[0][1], af[0][2], af[0][3], pb + a_lm[0] + kb);
            LDSM_X4(af[1][0], af[1][1], af[1][2], af[1][3], pb + a_lm[1] + kb);
            u32 bf[8][2];
            LDSM_X4(bf[0][0], bf[0][1], bf[1][0], bf[1][1], pb + b_lm[0] + kb);
            LDSM_X4(bf[2][0], bf[2][1], bf[3][0], bf[3][1], pb + b_lm[1] + kb);
            LDSM_X4(bf[4][0], bf[4][1], bf[5][0], bf[5][1], pb + b_lm[2] + kb);
            LDSM_X4(bf[6][0], bf[6][1], bf[7][0], bf[7][1], pb + b_lm[3] + kb);
#pragma unroll
            for (int nt = 0; nt < 8; nt++)
#pragma unroll
                for (int ms = 0; ms < 2; ms++)
                    MMA16816(acc[ms * 8 + nt],
                             af[ms][0], af[ms][1], af[ms][2], af[ms][3],
                             bf[nt][0], bf[nt][1]);
        }
    }

    // ---- epilogue ----
#pragma unroll
    for (int ms = 0; ms < 2; ms++) {
#pragma unroll
        for (int half = 0; half < 2; half++) {
            int rloc = row0 + wm * 32 + ms * 16 + g + half * 8;
            if (rloc >= M) continue;
            int gslot = base + rloc;
            if (LAYER == 1) {
                __half* hrow = g_h + (size_t)gslot * DIM;
#pragma unroll
                for (int nt = 0; nt < 8; nt++) {
                    int col = bn0 + wn * 64 + nt * 8 + q * 2;
                    float b0 = bp[col], b1 = bp[col + 1];
                    float v0 = fmaxf(acc[ms * 8 + nt][half * 2 + 0] + b0, 0.f);
                    float v1 = fmaxf(acc[ms * 8 + nt][half * 2 + 1] + b1, 0.f);
                    *(__half2*)(hrow + col) =
                        __halves2half2(__float2half_rn(v0), __float2half_rn(v1));
                }
            } else {
                float* yrow = g_ye + (size_t)gslot * DIM;
#pragma unroll
                for (int nt = 0; nt < 8; nt++) {
                    int col = bn0 + wn * 64 + nt * 8 + q * 2;
                    float b0 = bp[col], b1 = bp[col + 1];
                    *(float2*)(yrow + col) =
                        make_float2(acc[ms * 8 + nt][half * 2 + 0] + b0,
                                    acc[ms * 8 + nt][half * 2 + 1] + b1);
                }
            }
        }
    }
}

// ---------------- combine: y[t] = w0*ye[slot0] + w1*ye[slot1] ----------------
__global__ void combine_kernel(float* __restrict__ y) {
    int idx = blockIdx.x * blockDim.x + threadIdx.x;    // over N_TOK * DIM/4
    int t  = idx >> 8;                                  // DIM/4 = 256
    int c4 = (idx & 255) * 4;
    float w0 = g_topw[2 * t],     w1 = g_topw[2 * t + 1];
    int   s0 = g_slot[2 * t],     s1 = g_slot[2 * t + 1];
    float4 a = *(const float4*)(g_ye + (size_t)s0 * DIM + c4);
    float4 b = *(const float4*)(g_ye + (size_t)s1 * DIM + c4);
    float4 v;
    v.x = w0 * a.x + w1 * b.x;
    v.y = w0 * a.y + w1 * b.y;
    v.z = w0 * a.z + w1 * b.z;
    v.w = w0 * a.w + w1 * b.w;
    *(float4*)(y + (size_t)t * DIM + c4) = v;
}

// ---------------- launch ----------------
extern "C" void kernel_launch(void* const* d_in, const int* in_sizes, int n_in,
                              void* d_out, int out_size) {
    const float* x  = (const float*)d_in[0];
    const float* Wg = (const float*)d_in[1];
    const float* bg = (const float*)d_in[2];
    const float* W1 = (const float*)d_in[3];
    const float* b1 = (const float*)d_in[4];
    const float* W2 = (const float*)d_in[5];
    const float* b2 = (const float*)d_in[6];

    float* y        = (float*)d_out;
    float* gate_out = (float*)d_out + (size_t)N_TOK * DIM;

    static int attr_done = 0;
    if (!attr_done) {
        cudaFuncSetAttribute(moe_hmma_kernel<1>,
            cudaFuncAttributeMaxDynamicSharedMemorySize, SMEM_B);
        cudaFuncSetAttribute(moe_hmma_kernel<2>,
            cudaFuncAttributeMaxDynamicSharedMemorySize, SMEM_B);
        attr_done = 1;
    }

    init_kernel<<<1, 32>>>();
    convert_w_kernel<<<dim3(DIM / 64, DIM / 32, 16), 256>>>(W1, W2);
    gate_kernel<<<N_TOK / 8, 256>>>(x, Wg, bg, gate_out);
    scan_kernel<<<1, 1>>>();
    route_kernel<<<NR / 256, 256>>>();

    dim3 grid(DIM / 128, NR / 128, NE);
    moe_hmma_kernel<1><<<grid, 256, SMEM_B>>>(b1);
    moe_hmma_kernel<2><<<grid, 256, SMEM_B>>>(b2);
    combine_kernel<<<(N_TOK * DIM / 4) / 256, 256>>>(y);
}